// round 15
// baseline (speedup 1.0000x reference)
#include <cuda_runtime.h>
#include <cuda_fp16.h>
#include <cstdint>

// DiffUnpool: out[b] = S[b] @ x[b]
// R15: BOTH operands pre-converted to fp16 (S via new pre-pass; x as R12).
// GEMM has zero in-loop LDG/CVT/STS: A and B stream via cp.async in a
// 4-stage ring (3 in flight), one barrier per chunk, ks fragment ping-pong.
// Values + MMA order identical to R12 -> rel_err must be 2.794276e-4.

#define A_BUF 8192                    // 128 rows x 64B fp16
#define B_BUF 8192                    // 32 rows x 256B fp16
#define OFF_B (4 * A_BUF)             // 32768
#define SM_BYTES (4 * A_BUF + 4 * B_BUF)   // 65536 dynamic

__device__ __align__(16) __half g_S16[16 * 2048 * 256];  // 16.75 MB
__device__ __align__(16) __half g_X16[16 * 256 * 256];   // 2 MB

__global__ void convert_s(const float* __restrict__ S) {
    int i = blockIdx.x * blockDim.x + threadIdx.x;        // 0..1048575
    const float4* src = (const float4*)S;
    float4 v0 = src[2 * i], v1 = src[2 * i + 1];
    __half2 h0 = __floats2half2_rn(v0.x, v0.y);
    __half2 h1 = __floats2half2_rn(v0.z, v0.w);
    __half2 h2 = __floats2half2_rn(v1.x, v1.y);
    __half2 h3 = __floats2half2_rn(v1.z, v1.w);
    ((uint4*)g_S16)[i] = make_uint4(*(uint32_t*)&h0, *(uint32_t*)&h1,
                                    *(uint32_t*)&h2, *(uint32_t*)&h3);
}
__global__ void convert_x(const float* __restrict__ X) {
    int i = blockIdx.x * blockDim.x + threadIdx.x;        // 0..131071
    const float4* src = (const float4*)X;
    float4 v0 = src[2 * i], v1 = src[2 * i + 1];
    __half2 h0 = __floats2half2_rn(v0.x, v0.y);
    __half2 h1 = __floats2half2_rn(v0.z, v0.w);
    __half2 h2 = __floats2half2_rn(v1.x, v1.y);
    __half2 h3 = __floats2half2_rn(v1.z, v1.w);
    ((uint4*)g_X16)[i] = make_uint4(*(uint32_t*)&h0, *(uint32_t*)&h1,
                                    *(uint32_t*)&h2, *(uint32_t*)&h3);
}

static __device__ __forceinline__ uint32_t cvta_smem(const void* p) {
    uint32_t a;
    asm("{ .reg .u64 t; cvta.to.shared.u64 t, %1; cvt.u32.u64 %0, t; }"
        : "=r"(a) : "l"(p));
    return a;
}

#define CP16(dst, src) \
    asm volatile("cp.async.cg.shared.global [%0], [%1], 16;" :: "r"(dst), "l"(src))
#define CPCOMMIT() asm volatile("cp.async.commit_group;" ::: "memory")
#define CPWAIT2()  asm volatile("cp.async.wait_group 2;" ::: "memory")

#define LDSM4(r0, r1, r2, r3, a) \
    asm volatile("ldmatrix.sync.aligned.m8n8.x4.shared.b16 {%0,%1,%2,%3}, [%4];" \
                 : "=r"(r0), "=r"(r1), "=r"(r2), "=r"(r3) : "r"(a))
#define LDSM4T(r0, r1, r2, r3, a) \
    asm volatile("ldmatrix.sync.aligned.m8n8.x4.trans.shared.b16 {%0,%1,%2,%3}, [%4];" \
                 : "=r"(r0), "=r"(r1), "=r"(r2), "=r"(r3) : "r"(a))
#define MMAF16(d, a, b0, b1) \
    asm volatile("mma.sync.aligned.m16n8k16.row.col.f32.f16.f16.f32 " \
                 "{%0,%1,%2,%3},{%4,%5,%6,%7},{%8,%9},{%0,%1,%2,%3};" \
                 : "+f"((d)[0]), "+f"((d)[1]), "+f"((d)[2]), "+f"((d)[3]) \
                 : "r"((a)[0]), "r"((a)[1]), "r"((a)[2]), "r"((a)[3]), "r"(b0), "r"(b1))

extern __shared__ char smbuf[];

__global__ __launch_bounds__(128, 2)
void diffunpool_f16_v5(float* __restrict__ O) {
    const int nt = blockIdx.x;   // 0..1
    const int mt = blockIdx.y;   // 0..15
    const int b  = blockIdx.z;   // 0..15

    const __half* Sb = g_S16 + ((size_t)b * 2048 + (size_t)mt * 128) * 256;
    const __half* Xb = g_X16 + (size_t)b * 65536 + (size_t)nt * 128;
    float*        Ob = O + ((size_t)b * 2048 + (size_t)mt * 128) * 256 + (size_t)nt * 128;

    const int tid = threadIdx.x, wid = tid >> 5, lane = tid & 31;
    const int wm = (wid & 1) * 64;
    const int wn = (wid >> 1) * 64;
    const uint32_t sb = cvta_smem(smbuf);

    // ---- per-chunk cp.async: A (128 rows x 4 segs) + B (32 rows x 16 segs),
    //      4 pieces each per thread; both in one commit group.
    auto issue = [&](int c) {
        const uint32_t abuf = sb + (uint32_t)(c & 3) * A_BUF;
        const uint32_t bbuf = sb + OFF_B + (uint32_t)(c & 3) * B_BUF;
#pragma unroll
        for (int q = 0; q < 4; q++) {                 // A
            int flat = q * 128 + tid;
            int m = flat >> 2, s = flat & 3;
            const __half* src = Sb + (size_t)m * 256 + c * 32 + s * 8;
            uint32_t dst = abuf + (uint32_t)m * 64 + (uint32_t)((s ^ ((m >> 1) & 3)) << 4);
            CP16(dst, src);
        }
#pragma unroll
        for (int q = 0; q < 4; q++) {                 // B
            int flat = q * 128 + tid;
            int k = flat >> 4, s = flat & 15;
            const __half* src = Xb + (size_t)(c * 32 + k) * 256 + s * 8;
            uint32_t dst = bbuf + (uint32_t)k * 256 + (uint32_t)((s ^ (k & 7)) << 4);
            CP16(dst, src);
        }
        CPCOMMIT();
    };

    // ---- fragment addressing (R12 verbatim)
    const int m_low = (lane & 7) + 8 * ((lane >> 3) & 1);
    const int halfk = lane >> 4;
    uint32_t rowA[4], swzA[4];
#pragma unroll
    for (int mf = 0; mf < 4; mf++) {
        int row = wm + mf * 16 + m_low;
        rowA[mf] = (uint32_t)row * 64;
        swzA[mf] = (uint32_t)((row >> 1) & 3);
    }
    const int b_kl  = lane & 15;
    const int kswz  = b_kl & 7;
    const int b_c0  = (wn >> 3) + (lane >> 4);
    const uint32_t bRow = (uint32_t)b_kl * 256;

    float d[4][8][4];
#pragma unroll
    for (int mf = 0; mf < 4; mf++)
#pragma unroll
        for (int j = 0; j < 8; j++)
#pragma unroll
            for (int r = 0; r < 4; r++) d[mf][j][r] = 0.0f;

    issue(0);
    issue(1);
    issue(2);

    for (int c = 0; c < 8; c++) {
        const uint32_t aOff = (uint32_t)(c & 3) * A_BUF;
        const uint32_t bOff = (uint32_t)(c & 3) * B_BUF;

        CPWAIT2();                 // pending = {c+1, c+2}(+empties) -> chunk c done
        __syncthreads();           // the ONLY barrier per chunk

        uint32_t a[2][4][4], bb[2][4][4];   // ks ping-pong (no in-loop cvt)

        // ---- preload ks=0
#pragma unroll
        for (int mf = 0; mf < 4; mf++) {
            uint32_t seg  = (uint32_t)halfk;
            uint32_t addr = sb + aOff + rowA[mf] + ((seg ^ swzA[mf]) << 4);
            LDSM4(a[0][mf][0], a[0][mf][1], a[0][mf][2], a[0][mf][3], addr);
        }
        {
            const uint32_t bkoff = sb + OFF_B + bOff + bRow;
#pragma unroll
            for (int nb = 0; nb < 4; nb++) {
                uint32_t chunk = (uint32_t)((b_c0 + nb * 2) ^ kswz);
                LDSM4T(bb[0][nb][0], bb[0][nb][1], bb[0][nb][2], bb[0][nb][3],
                       bkoff + (chunk << 4));
            }
        }

#pragma unroll
        for (int ks = 0; ks < 2; ks++) {
            const int cur = ks & 1, nxt = cur ^ 1;
            // issue LDSM for ks+1 before MMAs of ks
            if (ks == 0) {
#pragma unroll
                for (int mf = 0; mf < 4; mf++) {
                    uint32_t seg  = (uint32_t)(2 + halfk);
                    uint32_t addr = sb + aOff + rowA[mf] + ((seg ^ swzA[mf]) << 4);
                    LDSM4(a[nxt][mf][0], a[nxt][mf][1], a[nxt][mf][2], a[nxt][mf][3], addr);
                }
                const uint32_t bkoff = sb + OFF_B + bOff + 4096 + bRow;
#pragma unroll
                for (int nb = 0; nb < 4; nb++) {
                    uint32_t chunk = (uint32_t)((b_c0 + nb * 2) ^ kswz);
                    LDSM4T(bb[nxt][nb][0], bb[nxt][nb][1], bb[nxt][nb][2], bb[nxt][nb][3],
                           bkoff + (chunk << 4));
                }
            }
#pragma unroll
            for (int mf = 0; mf < 4; mf++)
#pragma unroll
                for (int nb = 0; nb < 4; nb++) {
                    MMAF16(d[mf][2*nb],   a[cur][mf], bb[cur][nb][0], bb[cur][nb][1]);
                    MMAF16(d[mf][2*nb+1], a[cur][mf], bb[cur][nb][2], bb[cur][nb][3]);
                }
        }

        // ---- refill ring: buf (c+3)&3's last readers (compute c-1) passed sync(c)
        if (c < 5) issue(c + 3);
        else if (c < 7) CPCOMMIT();     // empty group keeps wait accounting exact
    }

    // ---- epilogue (R12 verbatim)
    const int group = lane >> 2;
    const int tcol  = (lane & 3) * 2;
#pragma unroll
    for (int mf = 0; mf < 4; mf++) {
        int m0 = wm + mf * 16 + group;
#pragma unroll
        for (int j = 0; j < 8; j++) {
            int n0 = wn + j * 8 + tcol;
            *(float2*)(Ob + (size_t)m0 * 256 + n0)       = make_float2(d[mf][j][0], d[mf][j][1]);
            *(float2*)(Ob + (size_t)(m0 + 8) * 256 + n0) = make_float2(d[mf][j][2], d[mf][j][3]);
        }
    }
}

extern "C" void kernel_launch(void* const* d_in, const int* in_sizes, int n_in,
                              void* d_out, int out_size) {
    const float* S = nullptr;
    const float* X = nullptr;
    for (int i = 0; i < n_in; i++) {
        if (in_sizes[i] == 8388608)      S = (const float*)d_in[i];
        else if (in_sizes[i] == 1048576) X = (const float*)d_in[i];
    }
    float* O = (float*)d_out;

    convert_s<<<4096, 256>>>(S);    // 1048576 threads x 8 floats
    convert_x<<<512, 256>>>(X);     // 131072 threads x 8 floats

    cudaFuncSetAttribute(diffunpool_f16_v5,
                         cudaFuncAttributeMaxDynamicSharedMemorySize, SM_BYTES);
    dim3 grid(2, 16, 16);
    diffunpool_f16_v5<<<grid, 128, SM_BYTES>>>(O);
}

// round 16
// speedup vs baseline: 1.0088x; 1.0088x over previous
#include <cuda_runtime.h>
#include <cuda_fp16.h>
#include <cstdint>

// DiffUnpool: out[b] = S[b] @ x[b]
// R16: (1) convert_s with MLP=4 (16 floats/thread) to approach DRAM roofline;
// (2) all-async GEMM (R15 ring, one barrier/chunk) with 8 warps of 64x32
// (R13 geometry, 64 acc/thread -> occ 2 -> 4 warps/SMSP).
// Values + accumulation order identical to R13/R15 -> rel_err 2.794276e-4.

#define A_BUF 8192                    // 128 rows x 64B fp16
#define B_BUF 8192                    // 32 rows x 256B fp16
#define OFF_B (4 * A_BUF)             // 32768
#define SM_BYTES (4 * A_BUF + 4 * B_BUF)   // 65536 dynamic

__device__ __align__(16) __half g_S16[16 * 2048 * 256];  // 16.75 MB
__device__ __align__(16) __half g_X16[16 * 256 * 256];   // 2 MB

static __device__ __forceinline__ uint32_t h2u(float x, float y) {
    __half2 h = __floats2half2_rn(x, y);
    return *(uint32_t*)&h;
}

// 16 floats per thread, 4 independent LDG.128 in flight (MLP=4)
__global__ void convert_s(const float* __restrict__ S) {
    int i = blockIdx.x * blockDim.x + threadIdx.x;        // 0..524287
    const float4* src = (const float4*)S + (size_t)i * 4;
    float4 v0 = src[0], v1 = src[1], v2 = src[2], v3 = src[3];
    uint4 o0 = make_uint4(h2u(v0.x, v0.y), h2u(v0.z, v0.w),
                          h2u(v1.x, v1.y), h2u(v1.z, v1.w));
    uint4 o1 = make_uint4(h2u(v2.x, v2.y), h2u(v2.z, v2.w),
                          h2u(v3.x, v3.y), h2u(v3.z, v3.w));
    ((uint4*)g_S16)[2 * i]     = o0;
    ((uint4*)g_S16)[2 * i + 1] = o1;
}
__global__ void convert_x(const float* __restrict__ X) {
    int i = blockIdx.x * blockDim.x + threadIdx.x;        // 0..65535
    const float4* src = (const float4*)X + (size_t)i * 4;
    float4 v0 = src[0], v1 = src[1], v2 = src[2], v3 = src[3];
    uint4 o0 = make_uint4(h2u(v0.x, v0.y), h2u(v0.z, v0.w),
                          h2u(v1.x, v1.y), h2u(v1.z, v1.w));
    uint4 o1 = make_uint4(h2u(v2.x, v2.y), h2u(v2.z, v2.w),
                          h2u(v3.x, v3.y), h2u(v3.z, v3.w));
    ((uint4*)g_X16)[2 * i]     = o0;
    ((uint4*)g_X16)[2 * i + 1] = o1;
}

static __device__ __forceinline__ uint32_t cvta_smem(const void* p) {
    uint32_t a;
    asm("{ .reg .u64 t; cvta.to.shared.u64 t, %1; cvt.u32.u64 %0, t; }"
        : "=r"(a) : "l"(p));
    return a;
}

#define CP16(dst, src) \
    asm volatile("cp.async.cg.shared.global [%0], [%1], 16;" :: "r"(dst), "l"(src))
#define CPCOMMIT() asm volatile("cp.async.commit_group;" ::: "memory")
#define CPWAIT2()  asm volatile("cp.async.wait_group 2;" ::: "memory")

#define LDSM4(r0, r1, r2, r3, a) \
    asm volatile("ldmatrix.sync.aligned.m8n8.x4.shared.b16 {%0,%1,%2,%3}, [%4];" \
                 : "=r"(r0), "=r"(r1), "=r"(r2), "=r"(r3) : "r"(a))
#define LDSM4T(r0, r1, r2, r3, a) \
    asm volatile("ldmatrix.sync.aligned.m8n8.x4.trans.shared.b16 {%0,%1,%2,%3}, [%4];" \
                 : "=r"(r0), "=r"(r1), "=r"(r2), "=r"(r3) : "r"(a))
#define MMAF16(d, a, b0, b1) \
    asm volatile("mma.sync.aligned.m16n8k16.row.col.f32.f16.f16.f32 " \
                 "{%0,%1,%2,%3},{%4,%5,%6,%7},{%8,%9},{%0,%1,%2,%3};" \
                 : "+f"((d)[0]), "+f"((d)[1]), "+f"((d)[2]), "+f"((d)[3]) \
                 : "r"((a)[0]), "r"((a)[1]), "r"((a)[2]), "r"((a)[3]), "r"(b0), "r"(b1))

extern __shared__ char smbuf[];

__global__ __launch_bounds__(256, 2)
void diffunpool_f16_v6(float* __restrict__ O) {
    const int nt = blockIdx.x;   // 0..1
    const int mt = blockIdx.y;   // 0..15
    const int b  = blockIdx.z;   // 0..15

    const __half* Sb = g_S16 + ((size_t)b * 2048 + (size_t)mt * 128) * 256;
    const __half* Xb = g_X16 + (size_t)b * 65536 + (size_t)nt * 128;
    float*        Ob = O + ((size_t)b * 2048 + (size_t)mt * 128) * 256 + (size_t)nt * 128;

    const int tid = threadIdx.x, wid = tid >> 5, lane = tid & 31;
    const int wm = (wid & 1) * 64;       // 2 m-groups of 64
    const int wn = (wid >> 1) * 32;      // 4 n-groups of 32
    const uint32_t sb = cvta_smem(smbuf);

    // ---- per-chunk cp.async: A 512 pieces + B 512 pieces, 2 each per thread
    auto issue = [&](int c) {
        const uint32_t abuf = sb + (uint32_t)(c & 3) * A_BUF;
        const uint32_t bbuf = sb + OFF_B + (uint32_t)(c & 3) * B_BUF;
#pragma unroll
        for (int q = 0; q < 2; q++) {                 // A: 128 rows x 4 segs
            int flat = q * 256 + tid;
            int m = flat >> 2, s = flat & 3;
            const __half* src = Sb + (size_t)m * 256 + c * 32 + s * 8;
            uint32_t dst = abuf + (uint32_t)m * 64 + (uint32_t)((s ^ ((m >> 1) & 3)) << 4);
            CP16(dst, src);
        }
#pragma unroll
        for (int q = 0; q < 2; q++) {                 // B: 32 rows x 16 segs
            int flat = q * 256 + tid;
            int k = flat >> 4, s = flat & 15;
            const __half* src = Xb + (size_t)(c * 32 + k) * 256 + s * 8;
            uint32_t dst = bbuf + (uint32_t)k * 256 + (uint32_t)((s ^ (k & 7)) << 4);
            CP16(dst, src);
        }
        CPCOMMIT();
    };

    // ---- fragment addressing (R13 verbatim)
    const int m_low = (lane & 7) + 8 * ((lane >> 3) & 1);
    const int halfk = lane >> 4;
    uint32_t rowA[4], swzA[4];
#pragma unroll
    for (int mf = 0; mf < 4; mf++) {
        int row = wm + mf * 16 + m_low;
        rowA[mf] = (uint32_t)row * 64;
        swzA[mf] = (uint32_t)((row >> 1) & 3);
    }
    const int b_kl  = lane & 15;
    const int kswz  = b_kl & 7;
    const int b_c0  = (wn >> 3) + (lane >> 4);
    const uint32_t bRow = (uint32_t)b_kl * 256;

    float d[4][4][4];                                  // 64 accumulators
#pragma unroll
    for (int mf = 0; mf < 4; mf++)
#pragma unroll
        for (int j = 0; j < 4; j++)
#pragma unroll
            for (int r = 0; r < 4; r++) d[mf][j][r] = 0.0f;

    issue(0);
    issue(1);
    issue(2);

    for (int c = 0; c < 8; c++) {
        const uint32_t aOff = (uint32_t)(c & 3) * A_BUF;
        const uint32_t bOff = (uint32_t)(c & 3) * B_BUF;

        CPWAIT2();                 // pending <= {c+1, c+2} -> chunk c resident
        __syncthreads();           // the ONLY barrier per chunk

        // ---- compute chunk c: 2 k16 steps (R13 verbatim body)
#pragma unroll
        for (int ks = 0; ks < 2; ks++) {
            uint32_t a[4][4];
#pragma unroll
            for (int mf = 0; mf < 4; mf++) {
                uint32_t seg  = (uint32_t)(2 * ks + halfk);
                uint32_t addr = sb + aOff + rowA[mf] + ((seg ^ swzA[mf]) << 4);
                LDSM4(a[mf][0], a[mf][1], a[mf][2], a[mf][3], addr);
            }
            uint32_t bb[2][4];
            const uint32_t bkoff = sb + OFF_B + bOff + (uint32_t)(ks * 4096) + bRow;
#pragma unroll
            for (int nb = 0; nb < 2; nb++) {
                uint32_t chunk = (uint32_t)((b_c0 + nb * 2) ^ kswz);
                LDSM4T(bb[nb][0], bb[nb][1], bb[nb][2], bb[nb][3], bkoff + (chunk << 4));
            }
#pragma unroll
            for (int mf = 0; mf < 4; mf++)
#pragma unroll
                for (int nb = 0; nb < 2; nb++) {
                    MMAF16(d[mf][2*nb],   a[mf], bb[nb][0], bb[nb][1]);
                    MMAF16(d[mf][2*nb+1], a[mf], bb[nb][2], bb[nb][3]);
                }
        }

        // ---- refill: buf (c+3)&3's last readers (compute c-1) passed sync(c);
        //      empty commits keep "wait_group 2 == chunk c done" exact.
        if (c < 5) issue(c + 3);
        else if (c < 7) CPCOMMIT();
    }

    // ---- epilogue (R13 verbatim)
    const int group = lane >> 2;
    const int tcol  = (lane & 3) * 2;
#pragma unroll
    for (int mf = 0; mf < 4; mf++) {
        int m0 = wm + mf * 16 + group;
#pragma unroll
        for (int j = 0; j < 4; j++) {
            int n0 = wn + j * 8 + tcol;
            *(float2*)(Ob + (size_t)m0 * 256 + n0)       = make_float2(d[mf][j][0], d[mf][j][1]);
            *(float2*)(Ob + (size_t)(m0 + 8) * 256 + n0) = make_float2(d[mf][j][2], d[mf][j][3]);
        }
    }
}

extern "C" void kernel_launch(void* const* d_in, const int* in_sizes, int n_in,
                              void* d_out, int out_size) {
    const float* S = nullptr;
    const float* X = nullptr;
    for (int i = 0; i < n_in; i++) {
        if (in_sizes[i] == 8388608)      S = (const float*)d_in[i];
        else if (in_sizes[i] == 1048576) X = (const float*)d_in[i];
    }
    float* O = (float*)d_out;

    convert_s<<<2048, 256>>>(S);    // 524288 threads x 16 floats
    convert_x<<<256, 256>>>(X);     // 65536 threads x 16 floats

    cudaFuncSetAttribute(diffunpool_f16_v6,
                         cudaFuncAttributeMaxDynamicSharedMemorySize, SM_BYTES);
    dim3 grid(2, 16, 16);
    diffunpool_f16_v6<<<grid, 256, SM_BYTES>>>(O);
}

// round 17
// speedup vs baseline: 1.1750x; 1.1648x over previous
#include <cuda_runtime.h>
#include <cuda_fp16.h>
#include <cstdint>

// DiffUnpool: out[b] = S[b] @ x[b]
//   S: [16, 2048, 256] f32   x: [16, 256, 256] f32   out: [16, 2048, 256] f32
// R17 = R12 fused structure with: K-chunks of 64 (4 chunks, 4 barriers),
// A converted fp32->fp16 AT LOAD (held packed, halves staging regs),
// A smem rows of 128B (R6-proven swizzle), B 3-deep cp.async ring.
// Values + accumulation order identical to R12 -> rel_err 2.794276e-4.

#define KC 64
#define A_BUF 16384                   // 128 rows x 128B fp16
#define B_BUF 16384                   // 64 rows x 256B fp16
#define OFF_B (2 * A_BUF)             // 32768
#define SM_BYTES (2 * A_BUF + 3 * B_BUF)   // 81920

__device__ __align__(16) __half g_X16[16 * 256 * 256];   // 2 MB scratch

static __device__ __forceinline__ uint32_t h2u(float x, float y) {
    __half2 h = __floats2half2_rn(x, y);
    return *(uint32_t*)&h;
}
__global__ void convert_x(const float* __restrict__ X) {
    int i = blockIdx.x * blockDim.x + threadIdx.x;        // 0..131071
    const float4* src = (const float4*)X;
    float4 v0 = src[2 * i], v1 = src[2 * i + 1];
    ((uint4*)g_X16)[i] = make_uint4(h2u(v0.x, v0.y), h2u(v0.z, v0.w),
                                    h2u(v1.x, v1.y), h2u(v1.z, v1.w));
}

static __device__ __forceinline__ uint32_t cvta_smem(const void* p) {
    uint32_t a;
    asm("{ .reg .u64 t; cvta.to.shared.u64 t, %1; cvt.u32.u64 %0, t; }"
        : "=r"(a) : "l"(p));
    return a;
}
static __device__ __forceinline__ uint4 cvt8(float4 a, float4 b) {
    return make_uint4(h2u(a.x, a.y), h2u(a.z, a.w), h2u(b.x, b.y), h2u(b.z, b.w));
}

#define CP16(dst, src) \
    asm volatile("cp.async.cg.shared.global [%0], [%1], 16;" :: "r"(dst), "l"(src))
#define CPCOMMIT()  asm volatile("cp.async.commit_group;" ::: "memory")
#define CPWAIT(n)   asm volatile("cp.async.wait_group %0;" :: "n"(n) : "memory")

#define LDSM4(r0, r1, r2, r3, a) \
    asm volatile("ldmatrix.sync.aligned.m8n8.x4.shared.b16 {%0,%1,%2,%3}, [%4];" \
                 : "=r"(r0), "=r"(r1), "=r"(r2), "=r"(r3) : "r"(a))
#define LDSM4T(r0, r1, r2, r3, a) \
    asm volatile("ldmatrix.sync.aligned.m8n8.x4.trans.shared.b16 {%0,%1,%2,%3}, [%4];" \
                 : "=r"(r0), "=r"(r1), "=r"(r2), "=r"(r3) : "r"(a))
#define MMAF16(d, a, b0, b1) \
    asm volatile("mma.sync.aligned.m16n8k16.row.col.f32.f16.f16.f32 " \
                 "{%0,%1,%2,%3},{%4,%5,%6,%7},{%8,%9},{%0,%1,%2,%3};" \
                 : "+f"((d)[0]), "+f"((d)[1]), "+f"((d)[2]), "+f"((d)[3]) \
                 : "r"((a)[0]), "r"((a)[1]), "r"((a)[2]), "r"((a)[3]), "r"(b0), "r"(b1))

extern __shared__ char smbuf[];

__global__ __launch_bounds__(128, 2)
void diffunpool_f16_v7(const float* __restrict__ S, float* __restrict__ O) {
    const int nt = blockIdx.x;   // 0..1
    const int mt = blockIdx.y;   // 0..15
    const int b  = blockIdx.z;   // 0..15

    const float*  Sb = S + ((size_t)b * 2048 + (size_t)mt * 128) * 256;
    const __half* Xb = g_X16 + (size_t)b * 65536 + (size_t)nt * 128;
    float*        Ob = O + ((size_t)b * 2048 + (size_t)mt * 128) * 256 + (size_t)nt * 128;

    const int tid = threadIdx.x, wid = tid >> 5, lane = tid & 31;
    const int wm = (wid & 1) * 64;
    const int wn = (wid >> 1) * 64;
    const uint32_t sb = cvta_smem(smbuf);

    // ---- A staging: 1024 pieces (128 rows x 8 segs of 8 floats), 8/thread.
    //      LDG fp32 -> cvt at load -> hold uint4 -> STS.128 with seg^(m&7).
    const int a_m0 = tid >> 3, a_s = tid & 7;     // q adds 16 rows
    const float*   pA    = Sb + (size_t)a_m0 * 256 + a_s * 8;
    const uint32_t aSts0 = (uint32_t)a_m0 * 128 + (uint32_t)((a_s ^ (a_m0 & 7)) << 4);
    // per q: m = a_m0 + 16q -> row offset +2048B; swizzle key (m&7) unchanged by +16q.

    // ---- B cp.async: 1024 pieces (64 rows x 16 segs), 8/thread, 3-ring
    auto issueB = [&](int c) {
        const uint32_t bbuf = sb + OFF_B + (uint32_t)(c % 3) * B_BUF;
#pragma unroll
        for (int q = 0; q < 8; q++) {
            int flat = q * 128 + tid;
            int k = flat >> 4, s = flat & 15;
            const __half* src = Xb + (size_t)(c * KC + k) * 256 + s * 8;
            uint32_t dst = bbuf + (uint32_t)k * 256 + (uint32_t)((s ^ (k & 7)) << 4);
            CP16(dst, src);
        }
        CPCOMMIT();
    };

    // ---- fragment addressing
    const int m_low = (lane & 7) + 8 * ((lane >> 3) & 1);
    const int sw    = lane & 7;                  // = m_low & 7
    const int halfk = lane >> 4;
    uint32_t rowA[4];
#pragma unroll
    for (int mf = 0; mf < 4; mf++)
        rowA[mf] = (uint32_t)(wm + mf * 16 + m_low) * 128;
    const int b_kl  = lane & 15;
    const int kswz  = b_kl & 7;
    const int b_c0  = (wn >> 3) + (lane >> 4);
    const uint32_t bRow = (uint32_t)b_kl * 256;

    float d[4][8][4];
#pragma unroll
    for (int mf = 0; mf < 4; mf++)
#pragma unroll
        for (int j = 0; j < 8; j++)
#pragma unroll
            for (int r = 0; r < 4; r++) d[mf][j][r] = 0.0f;

    // ---- prologue: B chunks 0,1,2 in flight; A chunk 0 loaded+converted
    issueB(0); issueB(1); issueB(2);
    uint4 ha[8];
#pragma unroll
    for (int q = 0; q < 8; q++) {
        const float* p = pA + (size_t)q * 4096;           // +16 rows
        ha[q] = cvt8(*(const float4*)p, *(const float4*)(p + 4));
    }

#pragma unroll
    for (int c = 0; c < 4; c++) {
        const uint32_t aOff = (uint32_t)(c & 1) * A_BUF;
        const uint32_t bOff = (uint32_t)(c % 3) * B_BUF;

        // ---- STS A(c): buf (c&1) last read by compute(c-2), pre-sync(c-1)
#pragma unroll
        for (int q = 0; q < 8; q++)
            *(uint4*)(smbuf + aOff + aSts0 + q * 2048) = ha[q];

        // ---- wait B(c): exact group accounting (3 issued up front, 1 at c==1)
        if (c == 0)      CPWAIT(2);
        else if (c == 3) CPWAIT(0);
        else             CPWAIT(1);
        __syncthreads();

        // ---- B(3) refill: buf 0's readers (compute(0)) all passed sync(1)
        if (c == 1) issueB(3);

        // ---- LDG+cvt A(c+1) (consumed at STS top of next chunk)
        if (c < 3) {
            const float* nA = pA + (c + 1) * KC;
#pragma unroll
            for (int q = 0; q < 8; q++) {
                const float* p = nA + (size_t)q * 4096;
                ha[q] = cvt8(*(const float4*)p, *(const float4*)(p + 4));
            }
        }

        // ---- compute chunk c: 4 k16 steps
#pragma unroll
        for (int ks = 0; ks < 4; ks++) {
            uint32_t a[4][4];
            const uint32_t segsw = (uint32_t)(((2 * ks + halfk) ^ sw) << 4);
#pragma unroll
            for (int mf = 0; mf < 4; mf++)
                LDSM4(a[mf][0], a[mf][1], a[mf][2], a[mf][3],
                      sb + aOff + rowA[mf] + segsw);
            uint32_t bb[4][4];
            const uint32_t bkoff = sb + OFF_B + bOff + (uint32_t)(ks * 4096) + bRow;
#pragma unroll
            for (int nb = 0; nb < 4; nb++) {
                uint32_t chunk = (uint32_t)((b_c0 + nb * 2) ^ kswz);
                LDSM4T(bb[nb][0], bb[nb][1], bb[nb][2], bb[nb][3], bkoff + (chunk << 4));
            }
#pragma unroll
            for (int mf = 0; mf < 4; mf++)
#pragma unroll
                for (int nb = 0; nb < 4; nb++) {
                    MMAF16(d[mf][2*nb],   a[mf], bb[nb][0], bb[nb][1]);
                    MMAF16(d[mf][2*nb+1], a[mf], bb[nb][2], bb[nb][3]);
                }
        }
    }

    // ---- epilogue (R12 verbatim)
    const int group = lane >> 2;
    const int tcol  = (lane & 3) * 2;
#pragma unroll
    for (int mf = 0; mf < 4; mf++) {
        int m0 = wm + mf * 16 + group;
#pragma unroll
        for (int j = 0; j < 8; j++) {
            int n0 = wn + j * 8 + tcol;
            *(float2*)(Ob + (size_t)m0 * 256 + n0)       = make_float2(d[mf][j][0], d[mf][j][1]);
            *(float2*)(Ob + (size_t)(m0 + 8) * 256 + n0) = make_float2(d[mf][j][2], d[mf][j][3]);
        }
    }
}

extern "C" void kernel_launch(void* const* d_in, const int* in_sizes, int n_in,
                              void* d_out, int out_size) {
    const float* S = nullptr;
    const float* X = nullptr;
    for (int i = 0; i < n_in; i++) {
        if (in_sizes[i] == 8388608)      S = (const float*)d_in[i];
        else if (in_sizes[i] == 1048576) X = (const float*)d_in[i];
    }
    float* O = (float*)d_out;

    convert_x<<<512, 256>>>(X);

    cudaFuncSetAttribute(diffunpool_f16_v7,
                         cudaFuncAttributeMaxDynamicSharedMemorySize, SM_BYTES);
    dim3 grid(2, 16, 16);
    diffunpool_f16_v7<<<grid, 128, SM_BYTES>>>(S, O);
}